// round 1
// baseline (speedup 1.0000x reference)
#include <cuda_runtime.h>
#include <cstdint>

// MXFP8 E4M3 quantize->dequantize, 32-element blocks along last axis.
// One thread handles 4 consecutive floats (float4); 8 threads = one MX block.
// Block amax via 3x shfl.xor (groups of 8 are warp-aligned).
//
// All scales are exact powers of two built by bit manipulation, so every
// multiply matches the reference's fp32 divide bit-for-bit. floor(log2(x))
// for fp32 normals == exponent field - 127 (exact).

static constexpr int EMAX = 8;           // e4m3
static constexpr float MAX_NORM = 448.0f;

__device__ __forceinline__ float quant_e4m3(float x, float iscale, float scale) {
    float a = x * iscale;                          // exact (iscale = 2^k)
    uint32_t au = __float_as_uint(a);
    uint32_t ab = au & 0x7fffffffu;                // |a|
    int pe = (int)(ab >> 23) - 127;                // floor(log2|a|), exact for normals
    pe = max(pe, -6);                              // MIN_EXP (denorm region clamp)
    // lshift = 2^(3-pe), inv_lshift = 2^(pe-3); pe in [-6, 8] -> both normal
    float lsh  = __uint_as_float((uint32_t)(130 - pe) << 23);
    float ilsh = __uint_as_float((uint32_t)(124 + pe) << 23);
    // round-half-away-from-zero on magnitude: product is exact, +0.5 rounds once (== ref)
    float r = floorf(__uint_as_float(ab) * lsh + 0.5f);
    float m = fminf(r * ilsh, MAX_NORM);           // saturate to e4m3 max normal
    float res = m * scale;
    // reapply sign (sign(0) handled: magnitude 0 -> +/-0, compares equal)
    return __uint_as_float(__float_as_uint(res) | (au & 0x80000000u));
}

__global__ void __launch_bounds__(256) mxq_kernel(const float4* __restrict__ in,
                                                  float4* __restrict__ out,
                                                  int n4) {
    int gid = blockIdx.x * blockDim.x + threadIdx.x;
    if (gid >= n4) return;

    float4 v = __ldcs(&in[gid]);

    // local amax of 4, then reduce across the 8 threads of this MX block
    float ax = fmaxf(fmaxf(fabsf(v.x), fabsf(v.y)), fmaxf(fabsf(v.z), fabsf(v.w)));
    ax = fmaxf(ax, __shfl_xor_sync(0xffffffffu, ax, 1));
    ax = fmaxf(ax, __shfl_xor_sync(0xffffffffu, ax, 2));
    ax = fmaxf(ax, __shfl_xor_sync(0xffffffffu, ax, 4));

    // shared_exp = floor(log2(amax)) - EMAX, clamped to >= -127
    int e = (int)(__float_as_uint(ax) >> 23);      // ax >= 0, no sign bit
    int se = e - 127 - EMAX;
    se = max(se, -127);
    // scale = 2^se (se=-127 -> bits 0 -> +0.0f; only for all-zero blocks, output 0 anyway)
    float scale  = __uint_as_float((uint32_t)(se + 127) << 23);
    float iscale = __uint_as_float((uint32_t)(127 - se) << 23);

    v.x = quant_e4m3(v.x, iscale, scale);
    v.y = quant_e4m3(v.y, iscale, scale);
    v.z = quant_e4m3(v.z, iscale, scale);
    v.w = quant_e4m3(v.w, iscale, scale);

    __stcs(&out[gid], v);
}

extern "C" void kernel_launch(void* const* d_in, const int* in_sizes, int n_in,
                              void* d_out, int out_size) {
    const float4* in = (const float4*)d_in[0];
    float4* out = (float4*)d_out;
    int n4 = out_size / 4;                         // 8192*8192/4 = 16,777,216
    int threads = 256;
    int blocks = (n4 + threads - 1) / threads;
    mxq_kernel<<<blocks, threads>>>(in, out, n4);
}

// round 2
// speedup vs baseline: 1.0479x; 1.0479x over previous
#include <cuda_runtime.h>
#include <cstdint>

// MXFP8 E4M3 quantize->dequantize, 32-element blocks along last axis.
// R2: 4-way ILP — each thread processes 4 independent float4s from 4
// coalesced streams, front-batching 4x LDG.128 per thread (MLP_p1=4)
// to push DRAM utilization from 73% toward the ~80% streaming ceiling.
//
// 8 threads = one MX block per stream; amax via 3x shfl.xor (xor 1,2,4),
// groups of 8 warp-aligned in every stream (stream stride is a multiple
// of 8 float4s).
//
// All scales are exact powers of two built by bit manipulation, so every
// multiply matches the reference's fp32 divide bit-for-bit.

static constexpr int EMAX = 8;           // e4m3
static constexpr float MAX_NORM = 448.0f;
static constexpr int ILP = 4;

__device__ __forceinline__ float quant_e4m3(float x, float iscale, float scale) {
    float a = x * iscale;                          // exact (iscale = 2^k)
    uint32_t au = __float_as_uint(a);
    uint32_t ab = au & 0x7fffffffu;                // |a|
    int pe = (int)(ab >> 23) - 127;                // floor(log2|a|), exact for normals
    pe = max(pe, -6);                              // MIN_EXP (denorm region clamp)
    // lshift = 2^(3-pe), inv_lshift = 2^(pe-3); pe in [-6, 8] -> both normal
    float lsh  = __uint_as_float((uint32_t)(130 - pe) << 23);
    float ilsh = __uint_as_float((uint32_t)(124 + pe) << 23);
    // round-half-away-from-zero on magnitude: product is exact, +0.5 rounds once
    float r = floorf(__uint_as_float(ab) * lsh + 0.5f);
    float m = fminf(r * ilsh, MAX_NORM);           // saturate to e4m3 max normal
    float res = m * scale;
    return __uint_as_float(__float_as_uint(res) | (au & 0x80000000u));
}

__device__ __forceinline__ float4 process4(float4 v) {
    float ax = fmaxf(fmaxf(fabsf(v.x), fabsf(v.y)), fmaxf(fabsf(v.z), fabsf(v.w)));
    ax = fmaxf(ax, __shfl_xor_sync(0xffffffffu, ax, 1));
    ax = fmaxf(ax, __shfl_xor_sync(0xffffffffu, ax, 2));
    ax = fmaxf(ax, __shfl_xor_sync(0xffffffffu, ax, 4));

    int e = (int)(__float_as_uint(ax) >> 23);      // ax >= 0, no sign bit
    int se = e - 127 - EMAX;
    se = max(se, -127);
    float scale  = __uint_as_float((uint32_t)(se + 127) << 23);
    float iscale = __uint_as_float((uint32_t)(127 - se) << 23);

    v.x = quant_e4m3(v.x, iscale, scale);
    v.y = quant_e4m3(v.y, iscale, scale);
    v.z = quant_e4m3(v.z, iscale, scale);
    v.w = quant_e4m3(v.w, iscale, scale);
    return v;
}

__global__ void __launch_bounds__(256) mxq_kernel(const float4* __restrict__ in,
                                                  float4* __restrict__ out,
                                                  int stride) {
    int gid = blockIdx.x * blockDim.x + threadIdx.x;

    // Front-batched independent loads (MLP_p1 = 4)
    float4 v0 = __ldcs(&in[gid]);
    float4 v1 = __ldcs(&in[gid + stride]);
    float4 v2 = __ldcs(&in[gid + 2 * stride]);
    float4 v3 = __ldcs(&in[gid + 3 * stride]);

    v0 = process4(v0);
    v1 = process4(v1);
    v2 = process4(v2);
    v3 = process4(v3);

    __stcs(&out[gid], v0);
    __stcs(&out[gid + stride], v1);
    __stcs(&out[gid + 2 * stride], v2);
    __stcs(&out[gid + 3 * stride], v3);
}

extern "C" void kernel_launch(void* const* d_in, const int* in_sizes, int n_in,
                              void* d_out, int out_size) {
    const float4* in = (const float4*)d_in[0];
    float4* out = (float4*)d_out;
    int n4 = out_size / 4;                         // 16,777,216 float4s
    int threads = 256;
    int total_threads = n4 / ILP;                  // divides exactly (2^24 / 4)
    int blocks = total_threads / threads;          // 16384
    mxq_kernel<<<blocks, threads>>>(in, out, total_threads);
}

// round 3
// speedup vs baseline: 1.0508x; 1.0027x over previous
#include <cuda_runtime.h>
#include <cstdint>

// MXFP8 E4M3 quantize->dequantize, 32-element blocks along last axis.
// R3: 8-way ILP — each thread front-batches 8 independent LDG.128 from 8
// coalesced streams (MLP_p1=8), then processes+stores each stream in turn
// so data registers retire early. Target: DRAM 81% -> ~84%.
//
// 8 threads = one MX block per stream; amax via 3x shfl.xor (xor 1,2,4),
// groups of 8 warp-aligned in every stream (stream stride is a multiple
// of 8 float4s).
//
// All scales are exact powers of two built by bit manipulation, so every
// multiply matches the reference's fp32 divide bit-for-bit.

static constexpr int EMAX = 8;           // e4m3
static constexpr float MAX_NORM = 448.0f;
static constexpr int ILP = 8;

__device__ __forceinline__ float quant_e4m3(float x, float iscale, float scale) {
    float a = x * iscale;                          // exact (iscale = 2^k)
    uint32_t au = __float_as_uint(a);
    uint32_t ab = au & 0x7fffffffu;                // |a|
    int pe = (int)(ab >> 23) - 127;                // floor(log2|a|), exact for normals
    pe = max(pe, -6);                              // MIN_EXP (denorm region clamp)
    // lshift = 2^(3-pe), inv_lshift = 2^(pe-3); pe in [-6, 8] -> both normal
    float lsh  = __uint_as_float((uint32_t)(130 - pe) << 23);
    float ilsh = __uint_as_float((uint32_t)(124 + pe) << 23);
    // round-half-away-from-zero on magnitude: product is exact, +0.5 rounds once
    float r = floorf(__uint_as_float(ab) * lsh + 0.5f);
    float m = fminf(r * ilsh, MAX_NORM);           // saturate to e4m3 max normal
    float res = m * scale;
    return __uint_as_float(__float_as_uint(res) | (au & 0x80000000u));
}

__device__ __forceinline__ float4 process4(float4 v) {
    float ax = fmaxf(fmaxf(fabsf(v.x), fabsf(v.y)), fmaxf(fabsf(v.z), fabsf(v.w)));
    ax = fmaxf(ax, __shfl_xor_sync(0xffffffffu, ax, 1));
    ax = fmaxf(ax, __shfl_xor_sync(0xffffffffu, ax, 2));
    ax = fmaxf(ax, __shfl_xor_sync(0xffffffffu, ax, 4));

    int e = (int)(__float_as_uint(ax) >> 23);      // ax >= 0, no sign bit
    int se = e - 127 - EMAX;
    se = max(se, -127);
    float scale  = __uint_as_float((uint32_t)(se + 127) << 23);
    float iscale = __uint_as_float((uint32_t)(127 - se) << 23);

    v.x = quant_e4m3(v.x, iscale, scale);
    v.y = quant_e4m3(v.y, iscale, scale);
    v.z = quant_e4m3(v.z, iscale, scale);
    v.w = quant_e4m3(v.w, iscale, scale);
    return v;
}

__global__ void __launch_bounds__(256) mxq_kernel(const float4* __restrict__ in,
                                                  float4* __restrict__ out,
                                                  int stride) {
    int gid = blockIdx.x * blockDim.x + threadIdx.x;

    // Front-batched independent loads (MLP_p1 = 8)
    float4 v[ILP];
#pragma unroll
    for (int i = 0; i < ILP; i++)
        v[i] = __ldcs(&in[gid + i * stride]);

    // Process + store each stream as soon as its reduce completes, so data
    // registers retire early and nothing spills.
#pragma unroll
    for (int i = 0; i < ILP; i++) {
        float4 r = process4(v[i]);
        __stcs(&out[gid + i * stride], r);
    }
}

extern "C" void kernel_launch(void* const* d_in, const int* in_sizes, int n_in,
                              void* d_out, int out_size) {
    const float4* in = (const float4*)d_in[0];
    float4* out = (float4*)d_out;
    int n4 = out_size / 4;                         // 16,777,216 float4s
    int threads = 256;
    int total_threads = n4 / ILP;                  // 2,097,152 (multiple of 8)
    int blocks = total_threads / threads;          // 8192
    mxq_kernel<<<blocks, threads>>>(in, out, total_threads);
}